// round 15
// baseline (speedup 1.0000x reference)
#include <cuda_runtime.h>
#include <cuda_fp16.h>
#include <math.h>
#include <stdint.h>

#define B_ 32
#define S_ 2048
#define H_ 1024
#define D_ 2048     // H * L
#define MROWS 65536 // B*S

// ---------------- scratch (device globals; no runtime alloc) ----------------
__device__ float g_qpart[8 * B_ * H_];                     // qproj k-split partials
__device__ float g_spart[8 * MROWS];                       // partial scores per 128-h block
__device__ float g_cpart[16 * B_ * H_];                    // context partials
__device__ __align__(128) __half g_keys_h[(size_t)MROWS * H_];   // keys fp16 (rn)
__device__ __align__(128) __half g_UaT_h[H_ * H_];         // Ua^T fp16 (rn) [h][d]

// ---------------- PTX helpers (base PTX only) ----------------
__device__ __forceinline__ uint32_t smem_u32(const void* p) {
    uint32_t a;
    asm("{ .reg .u64 t; cvta.to.shared.u64 t, %1; cvt.u32.u64 %0, t; }" : "=r"(a) : "l"(p));
    return a;
}
__device__ __forceinline__ void cpasync16(uint32_t dst, const void* src) {
    asm volatile("cp.async.cg.shared.global [%0], [%1], 16;" :: "r"(dst), "l"(src));
}
#define CP_COMMIT() asm volatile("cp.async.commit_group;" ::: "memory")
#define CP_WAIT1()  asm volatile("cp.async.wait_group 1;" ::: "memory")
#define CP_WAIT0()  asm volatile("cp.async.wait_group 0;" ::: "memory")

__device__ __forceinline__ void ldsm4(uint32_t (&r)[4], uint32_t a) {
    asm volatile("ldmatrix.sync.aligned.m8n8.x4.shared.b16 {%0,%1,%2,%3}, [%4];"
                 : "=r"(r[0]), "=r"(r[1]), "=r"(r[2]), "=r"(r[3]) : "r"(a));
}
__device__ __forceinline__ void mma_f32(float (&d)[4], const uint32_t (&a)[4],
                                        uint32_t b0, uint32_t b1) {
    asm volatile(
        "mma.sync.aligned.m16n8k16.row.col.f32.f16.f16.f32 "
        "{%0,%1,%2,%3}, {%4,%5,%6,%7}, {%8,%9}, {%0,%1,%2,%3};"
        : "+f"(d[0]), "+f"(d[1]), "+f"(d[2]), "+f"(d[3])
        : "r"(a[0]), "r"(a[1]), "r"(a[2]), "r"(a[3]), "r"(b0), "r"(b1));
}

// pair-line swizzle: 64B rows, two rows per 128B line; steps of 16 rows = +1024B,
// 64 rows = +4096B (swizzle bits invariant).
__device__ __forceinline__ uint32_t swb(int r, int c) {
    return (uint32_t)((r >> 1) * 128 + ((((r & 1) << 2) | c) ^ ((r >> 1) & 7)) * 16);
}

__device__ __forceinline__ float tanh_fast(float x) {
    float e = __expf(-2.f * fabsf(x));
    return copysignf(__fdividef(1.f - e, 1.f + e), x);
}

// ============================================================
// P0 (fused preprocess): one launch, blockIdx ranges.
//  [0, 2048):    keys fp32 -> fp16 grid-stride split
//  [2048, 3072): Ua transpose + fp16
//  [3072, 3584): qproj partials (2-batch, 8-way K-split)
// ============================================================
__global__ __launch_bounds__(256) void preprocess_kernel(
    const float* __restrict__ keys, const float* __restrict__ Ua,
    const float* __restrict__ query, const float* __restrict__ Wa)
{
    __shared__ float tile[32][33];
    const int bid = blockIdx.x;

    if (bid < 2048) {
        // ---- keys split ----
        const size_t stride = (size_t)2048 * 256 * 8;
        size_t base = ((size_t)bid * 256 + threadIdx.x) * 8;
        #pragma unroll 4
        for (int it = 0; it < 16; it++) {
            size_t i = base + (size_t)it * stride;
            float4 v0 = *(const float4*)(keys + i);
            float4 v1 = *(const float4*)(keys + i + 4);
            __half2 h0 = __floats2half2_rn(v0.x, v0.y);
            __half2 h1 = __floats2half2_rn(v0.z, v0.w);
            __half2 h2 = __floats2half2_rn(v1.x, v1.y);
            __half2 h3 = __floats2half2_rn(v1.z, v1.w);
            uint4 o;
            o.x = *(uint32_t*)&h0; o.y = *(uint32_t*)&h1;
            o.z = *(uint32_t*)&h2; o.w = *(uint32_t*)&h3;
            *(uint4*)(g_keys_h + i) = o;
        }
    } else if (bid < 3072) {
        // ---- Ua transpose + fp16 ----
        int id = bid - 2048;
        int tx = threadIdx.x & 31, ty = threadIdx.x >> 5;
        int x0 = (id & 31) * 32, y0 = (id >> 5) * 32;   // x: h, y: d
        #pragma unroll
        for (int j = 0; j < 4; j++)
            tile[ty + j * 8][tx] = Ua[(size_t)(y0 + ty + j * 8) * H_ + x0 + tx];
        __syncthreads();
        #pragma unroll
        for (int j = 0; j < 4; j++) {
            float v = tile[tx][ty + j * 8];
            g_UaT_h[(size_t)(x0 + ty + j * 8) * H_ + y0 + tx] = __float2half_rn(v);
        }
    } else {
        // ---- qproj partials ----
        int id = bid - 3072;                 // 512 blocks: 4 hx * 16 bgrp * 8 kc
        int hx = id & 3;
        int b0 = ((id >> 2) & 15) * 2;
        int kc = id >> 6;
        const int h = hx * 256 + threadIdx.x;
        const float* q0 = query + (size_t)(b0 + 0) * D_ + kc * 256;
        const float* q1 = query + (size_t)(b0 + 1) * D_ + kc * 256;
        const float* w  = Wa + (size_t)kc * 256 * H_ + h;
        float a0 = 0.f, a1 = 0.f;
        #pragma unroll 8
        for (int d = 0; d < 256; d++) {
            float wv = w[(size_t)d * H_];
            a0 = fmaf(q0[d], wv, a0);
            a1 = fmaf(q1[d], wv, a1);
        }
        float* dst = g_qpart + (size_t)kc * (B_ * H_) + (size_t)b0 * H_ + h;
        dst[0]  = a0;
        dst[H_] = a1;
    }
}

// ============================================================
// K2: mma.sync score kernel v12 — BK=64 stages (two k32 sub-tiles),
// 3-buffer ring, 16 wait/barrier blocks (was 32). 2 CTAs/SM.
// 256 threads, CTA 128(s) x 128(h), 8 warps (4m x 2n), warp 32x64.
// Stage layout: A0 @0 | B0 @8192 | A1 @16384 | B1 @24576 (each 8K).
// grid (8 hblk, 512 sblk), h fastest for L2 reuse of A.
// ============================================================
#define STAGE  32768
#define OFS_B  8192
#define NSTG   3
#define SMEM_SCORE (NSTG * STAGE + 1024)

__global__ __launch_bounds__(256, 2) void score_kernel(
    const float* __restrict__ Va,
    const float* __restrict__ Wab, const float* __restrict__ Uab)
{
    extern __shared__ char smem[];
    const uint32_t sb = smem_u32(smem);
    const int tid  = threadIdx.x;
    const int wid  = tid >> 5, lane = tid & 31;
    const int wm   = wid & 3,  wn   = wid >> 2;      // 4m x 2n warp grid

    const int h0    = blockIdx.x * 128;
    const int grow0 = blockIdx.y * 128;
    const int b     = grow0 >> 11;

    float* qs = (float*)(smem + NSTG * STAGE);
    float* vs = qs + 128;
    if (tid < 128) {
        int h = h0 + tid;
        float s = Wab[h] + Uab[h];
        #pragma unroll
        for (int c = 0; c < 8; c++)
            s += g_qpart[(size_t)c * (B_ * H_) + (size_t)b * H_ + h];
        qs[tid] = s;
        vs[tid] = Va[h];
    }

    // ---- cp.async setup (bases include sb; stage offsets are immediates) ----
    const int cr = tid >> 2, cc = tid & 3;           // rows 0..63, chunks 0..3
    const __half* srcA = g_keys_h + (size_t)(grow0 + cr) * H_ + cc * 8;
    const __half* srcB = g_UaT_h  + (size_t)(h0 + cr) * H_ + cc * 8;
    const uint32_t dstA = sb + swb(cr, cc);
    const uint32_t dstB = sb + OFS_B + swb(cr, cc);

    // one BK=64 stage: two k32 sub-tiles (cols +0 and +32)
    #define ISSUE_STAGE(off) do {                                           \
        cpasync16(dstA + (off),         srcA);                              \
        cpasync16(dstA + (off) + 4096,  srcA + 64 * H_);                    \
        cpasync16(dstB + (off),         srcB);                              \
        cpasync16(dstB + (off) + 4096,  srcB + 64 * H_);                    \
        cpasync16(dstA + (off) + 16384, srcA + 32);                         \
        cpasync16(dstA + (off) + 20480, srcA + 32 + 64 * H_);               \
        cpasync16(dstB + (off) + 16384, srcB + 32);                         \
        cpasync16(dstB + (off) + 20480, srcB + 32 + 64 * H_);               \
        srcA += 64; srcB += 64;                                             \
    } while (0)

    // ---- ldmatrix bases (include sb) ----
    const int lrow = lane & 15, lcol = lane >> 4;
    uint32_t aoff[2], boff[2];
    #pragma unroll
    for (int ks = 0; ks < 2; ks++) {
        aoff[ks] = sb + swb(wm * 32 + lrow, ks * 2 + lcol);
        boff[ks] = sb + OFS_B + swb(wn * 64 + lrow, ks * 2 + lcol);
    }

    float acc[2][8][4];
    #pragma unroll
    for (int i = 0; i < 2; i++)
        #pragma unroll
        for (int j = 0; j < 8; j++)
            #pragma unroll
            for (int q = 0; q < 4; q++) acc[i][j][q] = 0.f;

    // compute one k32 sub-tile at byte offset `off`
    #define COMPUTE_SUB(off) do {                                           \
        _Pragma("unroll")                                                   \
        for (int ks = 0; ks < 2; ks++) {                                    \
            uint32_t ah[2][4];                                              \
            ldsm4(ah[0], aoff[ks] + (off));                                 \
            ldsm4(ah[1], aoff[ks] + (off) + 1024);                          \
            _Pragma("unroll")                                               \
            for (int ng = 0; ng < 4; ng++) {                                \
                uint32_t bh[4];                                             \
                ldsm4(bh, boff[ks] + (off) + ng * 1024);                    \
                const int nf = ng * 2;                                      \
                mma_f32(acc[0][nf],     ah[0], bh[0], bh[2]);               \
                mma_f32(acc[0][nf + 1], ah[0], bh[1], bh[3]);               \
                mma_f32(acc[1][nf],     ah[1], bh[0], bh[2]);               \
                mma_f32(acc[1][nf + 1], ah[1], bh[1], bh[3]);               \
            }                                                               \
        }                                                                   \
    } while (0)
    #define COMPUTE_STAGE(off) do {                                         \
        COMPUTE_SUB(off);                                                   \
        COMPUTE_SUB((off) + 16384);                                         \
    } while (0)

    // iteration u computes buffer u, refills buffer (u+2)%3
    #define ITER_FULL(u) do {                                               \
        CP_WAIT1();                                                         \
        __syncthreads();                                                    \
        ISSUE_STAGE((((u) + 2) % 3) * STAGE);                               \
        CP_COMMIT();                                                        \
        COMPUTE_STAGE((u) * STAGE);                                         \
    } while (0)
    #define ITER_TAIL(u, W) do {                                            \
        W();                                                                \
        __syncthreads();                                                    \
        CP_COMMIT();                                                        \
        COMPUTE_STAGE((u) * STAGE);                                         \
    } while (0)

    // prologue: stages 0, 1
    ISSUE_STAGE(0 * STAGE); CP_COMMIT();
    ISSUE_STAGE(1 * STAGE); CP_COMMIT();

    // 16 BK=64 iterations: k=0..11 in 4 blocks, then 12,13 full, 14,15 tail
    #pragma unroll 1
    for (int ob = 0; ob < 4; ob++) {
        ITER_FULL(0);
        ITER_FULL(1);
        ITER_FULL(2);
    }
    ITER_FULL(0);                 // k=12, refill buffer 2 (stage 14)
    ITER_FULL(1);                 // k=13, refill buffer 0 (stage 15)
    ITER_TAIL(2, CP_WAIT1);       // k=14
    ITER_TAIL(0, CP_WAIT0);       // k=15
    #undef ITER_FULL
    #undef ITER_TAIL

    // ---- epilogue: p[row] = sum_h tanh(acc + q[h]) * Va[h] ----
    float pr[2][2] = {{0.f, 0.f}, {0.f, 0.f}};
    #pragma unroll
    for (int ms = 0; ms < 2; ms++) {
        #pragma unroll
        for (int nf = 0; nf < 8; nf++) {
            int col = wn * 64 + nf * 8 + (lane & 3) * 2;
            float q0v = qs[col], q1v = qs[col + 1];
            float v0v = vs[col], v1v = vs[col + 1];
            pr[ms][0] += tanh_fast(acc[ms][nf][0] + q0v) * v0v
                       + tanh_fast(acc[ms][nf][1] + q1v) * v1v;
            pr[ms][1] += tanh_fast(acc[ms][nf][2] + q0v) * v0v
                       + tanh_fast(acc[ms][nf][3] + q1v) * v1v;
        }
    }
    #pragma unroll
    for (int ms = 0; ms < 2; ms++)
        #pragma unroll
        for (int hf = 0; hf < 2; hf++) {
            pr[ms][hf] += __shfl_xor_sync(0xFFFFFFFFu, pr[ms][hf], 1);
            pr[ms][hf] += __shfl_xor_sync(0xFFFFFFFFu, pr[ms][hf], 2);
        }

    __syncthreads();
    float* red = (float*)smem;            // 2 x 128 floats (stages dead)
    if ((lane & 3) == 0) {
        #pragma unroll
        for (int ms = 0; ms < 2; ms++) {
            int row = wm * 32 + ms * 16 + (lane >> 2);
            red[wn * 128 + row]     = pr[ms][0];
            red[wn * 128 + row + 8] = pr[ms][1];
        }
    }
    __syncthreads();
    if (tid < 128)
        g_spart[(size_t)blockIdx.x * MROWS + grow0 + tid] = red[tid] + red[128 + tid];
}

// ============================================================
// K3: softmax over S per batch (8 h-block partials)
// ============================================================
__global__ __launch_bounds__(256) void softmax_kernel(float* __restrict__ weights)
{
    const int b = blockIdx.x;
    const int tid = threadIdx.x;
    const int lane = tid & 31, wid = tid >> 5;
    __shared__ float sred[8];

    float v[8];
    #pragma unroll
    for (int i = 0; i < 8; i++) {
        int s = tid + i * 256;
        float t = 0.f;
        #pragma unroll
        for (int hb = 0; hb < 8; hb++)
            t += g_spart[(size_t)hb * MROWS + (size_t)b * S_ + s];
        v[i] = t;
    }
    float m = v[0];
    #pragma unroll
    for (int i = 1; i < 8; i++) m = fmaxf(m, v[i]);
    #pragma unroll
    for (int off = 16; off > 0; off >>= 1)
        m = fmaxf(m, __shfl_xor_sync(0xFFFFFFFFu, m, off));
    if (lane == 0) sred[wid] = m;
    __syncthreads();
    float mm = sred[0];
    #pragma unroll
    for (int w = 1; w < 8; w++) mm = fmaxf(mm, sred[w]);
    __syncthreads();
    float sum = 0.f;
    #pragma unroll
    for (int i = 0; i < 8; i++) { v[i] = __expf(v[i] - mm); sum += v[i]; }
    #pragma unroll
    for (int off = 16; off > 0; off >>= 1)
        sum += __shfl_xor_sync(0xFFFFFFFFu, sum, off);
    if (lane == 0) sred[wid] = sum;
    __syncthreads();
    float tot = 0.f;
    #pragma unroll
    for (int w = 0; w < 8; w++) tot += sred[w];
    float inv = 1.0f / tot;
    #pragma unroll
    for (int i = 0; i < 8; i++)
        weights[(size_t)b * S_ + tid + i * 256] = v[i] * inv;
}

// ============================================================
// K4: context partials, half2 loads, 16-way S split. grid (2, B, 16).
// ============================================================
__global__ __launch_bounds__(256) void context_part_kernel(
    const float* __restrict__ weights)
{
    const int b = blockIdx.y, sc = blockIdx.z;
    const int h2 = blockIdx.x * 256 + threadIdx.x;    // half2 index, 0..511
    __shared__ float sw[128];
    if (threadIdx.x < 128)
        sw[threadIdx.x] = weights[(size_t)b * S_ + sc * 128 + threadIdx.x];
    __syncthreads();

    const __half2* kb = (const __half2*)g_keys_h
                        + ((size_t)b * S_ + (size_t)sc * 128) * (H_ / 2) + h2;
    float ax0 = 0.f, ay0 = 0.f, ax1 = 0.f, ay1 = 0.f;
    #pragma unroll 4
    for (int s = 0; s < 128; s += 2) {
        float2 k0 = __half22float2(kb[(size_t)(s + 0) * (H_ / 2)]);
        float2 k1 = __half22float2(kb[(size_t)(s + 1) * (H_ / 2)]);
        ax0 = fmaf(sw[s + 0], k0.x, ax0);
        ay0 = fmaf(sw[s + 0], k0.y, ay0);
        ax1 = fmaf(sw[s + 1], k1.x, ax1);
        ay1 = fmaf(sw[s + 1], k1.y, ay1);
    }
    float* dst = g_cpart + (size_t)sc * (B_ * H_) + (size_t)b * H_ + h2 * 2;
    dst[0] = ax0 + ax1;
    dst[1] = ay0 + ay1;
}

__global__ __launch_bounds__(256) void context_reduce_kernel(float* __restrict__ ctx)
{
    int i = blockIdx.x * 256 + threadIdx.x;
    float s = 0.f;
    #pragma unroll
    for (int c = 0; c < 16; c++) s += g_cpart[(size_t)c * (B_ * H_) + i];
    ctx[i] = s;
}

// ============================================================
extern "C" void kernel_launch(void* const* d_in, const int* in_sizes, int n_in,
                              void* d_out, int out_size)
{
    const float* query = (const float*)d_in[0];
    const float* keys  = (const float*)d_in[1];
    const float* Wa_w  = (const float*)d_in[2];
    const float* Wa_b  = (const float*)d_in[3];
    const float* Ua_w  = (const float*)d_in[4];
    const float* Ua_b  = (const float*)d_in[5];
    const float* Va_w  = (const float*)d_in[6];
    // Va_b: constant shift of scores, cancels in softmax.

    float* ctx = (float*)d_out;
    float* wts = (float*)d_out + B_ * H_;

    cudaFuncSetAttribute(score_kernel,
                         cudaFuncAttributeMaxDynamicSharedMemorySize, SMEM_SCORE);

    preprocess_kernel<<<3584, 256>>>(keys, Ua_w, query, Wa_w);
    score_kernel<<<dim3(8, 512), 256, SMEM_SCORE>>>(Va_w, Wa_b, Ua_b);
    softmax_kernel<<<B_, 256>>>(wts);
    context_part_kernel<<<dim3(2, B_, 16), 256>>>(wts);
    context_reduce_kernel<<<(B_ * H_) / 256, 256>>>(ctx);
}

// round 16
// speedup vs baseline: 1.0494x; 1.0494x over previous
#include <cuda_runtime.h>
#include <cuda_fp16.h>
#include <math.h>
#include <stdint.h>

#define B_ 32
#define S_ 2048
#define H_ 1024
#define D_ 2048     // H * L
#define MROWS 65536 // B*S

// ---------------- scratch (device globals; no runtime alloc) ----------------
__device__ float g_qpart[8 * B_ * H_];                     // qproj k-split partials
__device__ float g_spart[8 * MROWS];                       // partial scores per 128-h block
__device__ __align__(128) __half g_keys_h[(size_t)MROWS * H_];   // keys fp16 (rn)
__device__ __align__(128) __half g_UaT_h[H_ * H_];         // Ua^T fp16 (rn) [h][d]

// ---------------- PTX helpers (base PTX only) ----------------
__device__ __forceinline__ uint32_t smem_u32(const void* p) {
    uint32_t a;
    asm("{ .reg .u64 t; cvta.to.shared.u64 t, %1; cvt.u32.u64 %0, t; }" : "=r"(a) : "l"(p));
    return a;
}
__device__ __forceinline__ void cpasync16(uint32_t dst, const void* src) {
    asm volatile("cp.async.cg.shared.global [%0], [%1], 16;" :: "r"(dst), "l"(src));
}
#define CP_COMMIT() asm volatile("cp.async.commit_group;" ::: "memory")
#define CP_WAIT2()  asm volatile("cp.async.wait_group 2;" ::: "memory")

__device__ __forceinline__ void ldsm4(uint32_t (&r)[4], uint32_t a) {
    asm volatile("ldmatrix.sync.aligned.m8n8.x4.shared.b16 {%0,%1,%2,%3}, [%4];"
                 : "=r"(r[0]), "=r"(r[1]), "=r"(r[2]), "=r"(r[3]) : "r"(a));
}
__device__ __forceinline__ void mma_f32(float (&d)[4], const uint32_t (&a)[4],
                                        uint32_t b0, uint32_t b1) {
    asm volatile(
        "mma.sync.aligned.m16n8k16.row.col.f32.f16.f16.f32 "
        "{%0,%1,%2,%3}, {%4,%5,%6,%7}, {%8,%9}, {%0,%1,%2,%3};"
        : "+f"(d[0]), "+f"(d[1]), "+f"(d[2]), "+f"(d[3])
        : "r"(a[0]), "r"(a[1]), "r"(a[2]), "r"(a[3]), "r"(b0), "r"(b1));
}

// pair-line swizzle: 64B rows, two rows per 128B line; steps of 16 rows = +1024B,
// 64 rows = +4096B (swizzle bits invariant).
__device__ __forceinline__ uint32_t swb(int r, int c) {
    return (uint32_t)((r >> 1) * 128 + ((((r & 1) << 2) | c) ^ ((r >> 1) & 7)) * 16);
}

__device__ __forceinline__ float tanh_fast(float x) {
    float e = __expf(-2.f * fabsf(x));
    return copysignf(__fdividef(1.f - e, 1.f + e), x);
}

// ============================================================
// P0 (fused preprocess): one launch, blockIdx ranges.
//  [0, 2048):    keys fp32 -> fp16 grid-stride split
//  [2048, 3072): Ua transpose + fp16
//  [3072, 3584): qproj partials (2-batch, 8-way K-split)
//  [3584, 3616): zero ctx (for context atomics)
// ============================================================
__global__ __launch_bounds__(256) void preprocess_kernel(
    const float* __restrict__ keys, const float* __restrict__ Ua,
    const float* __restrict__ query, const float* __restrict__ Wa,
    float* __restrict__ ctx)
{
    __shared__ float tile[32][33];
    const int bid = blockIdx.x;

    if (bid < 2048) {
        // ---- keys split ----
        const size_t stride = (size_t)2048 * 256 * 8;
        size_t base = ((size_t)bid * 256 + threadIdx.x) * 8;
        #pragma unroll 4
        for (int it = 0; it < 16; it++) {
            size_t i = base + (size_t)it * stride;
            float4 v0 = *(const float4*)(keys + i);
            float4 v1 = *(const float4*)(keys + i + 4);
            __half2 h0 = __floats2half2_rn(v0.x, v0.y);
            __half2 h1 = __floats2half2_rn(v0.z, v0.w);
            __half2 h2 = __floats2half2_rn(v1.x, v1.y);
            __half2 h3 = __floats2half2_rn(v1.z, v1.w);
            uint4 o;
            o.x = *(uint32_t*)&h0; o.y = *(uint32_t*)&h1;
            o.z = *(uint32_t*)&h2; o.w = *(uint32_t*)&h3;
            *(uint4*)(g_keys_h + i) = o;
        }
    } else if (bid < 3072) {
        // ---- Ua transpose + fp16 ----
        int id = bid - 2048;
        int tx = threadIdx.x & 31, ty = threadIdx.x >> 5;
        int x0 = (id & 31) * 32, y0 = (id >> 5) * 32;   // x: h, y: d
        #pragma unroll
        for (int j = 0; j < 4; j++)
            tile[ty + j * 8][tx] = Ua[(size_t)(y0 + ty + j * 8) * H_ + x0 + tx];
        __syncthreads();
        #pragma unroll
        for (int j = 0; j < 4; j++) {
            float v = tile[tx][ty + j * 8];
            g_UaT_h[(size_t)(x0 + ty + j * 8) * H_ + y0 + tx] = __float2half_rn(v);
        }
    } else if (bid < 3584) {
        // ---- qproj partials ----
        int id = bid - 3072;                 // 512 blocks: 4 hx * 16 bgrp * 8 kc
        int hx = id & 3;
        int b0 = ((id >> 2) & 15) * 2;
        int kc = id >> 6;
        const int h = hx * 256 + threadIdx.x;
        const float* q0 = query + (size_t)(b0 + 0) * D_ + kc * 256;
        const float* q1 = query + (size_t)(b0 + 1) * D_ + kc * 256;
        const float* w  = Wa + (size_t)kc * 256 * H_ + h;
        float a0 = 0.f, a1 = 0.f;
        #pragma unroll 8
        for (int d = 0; d < 256; d++) {
            float wv = w[(size_t)d * H_];
            a0 = fmaf(q0[d], wv, a0);
            a1 = fmaf(q1[d], wv, a1);
        }
        float* dst = g_qpart + (size_t)kc * (B_ * H_) + (size_t)b0 * H_ + h;
        dst[0]  = a0;
        dst[H_] = a1;
    } else {
        // ---- zero ctx (B_*H_ = 32768 floats; 32 blocks x 256 thr x 4) ----
        int id = bid - 3584;
        int i = (id * 256 + threadIdx.x) * 4;
        *(float4*)(ctx + i) = make_float4(0.f, 0.f, 0.f, 0.f);
    }
}

// ============================================================
// K2: mma.sync score kernel (r14 best config, unchanged).
// 256 threads, CTA 128(s) x 128(h), 8 warps (4m x 2n), warp 32x64.
// BK=32, 4-stage cp.async (wait_group 2), 2 CTAs/SM, unrolled.
// grid (8 hblk, 512 sblk), h fastest for L2 reuse of A.
// ============================================================
#define STAGE  16384          // A 8K | B 8K
#define OFS_B  8192
#define NSTG   4
#define SMEM_SCORE (NSTG * STAGE + 1024)

__global__ __launch_bounds__(256, 2) void score_kernel(
    const float* __restrict__ Va,
    const float* __restrict__ Wab, const float* __restrict__ Uab)
{
    extern __shared__ char smem[];
    const uint32_t sb = smem_u32(smem);
    const int tid  = threadIdx.x;
    const int wid  = tid >> 5, lane = tid & 31;
    const int wm   = wid & 3,  wn   = wid >> 2;      // 4m x 2n warp grid

    const int h0    = blockIdx.x * 128;
    const int grow0 = blockIdx.y * 128;
    const int b     = grow0 >> 11;

    float* qs = (float*)(smem + NSTG * STAGE);
    float* vs = qs + 128;
    if (tid < 128) {
        int h = h0 + tid;
        float s = Wab[h] + Uab[h];
        #pragma unroll
        for (int c = 0; c < 8; c++)
            s += g_qpart[(size_t)c * (B_ * H_) + (size_t)b * H_ + h];
        qs[tid] = s;
        vs[tid] = Va[h];
    }

    // ---- cp.async setup (bases include sb; stage offsets are immediates) ----
    const int cr = tid >> 2, cc = tid & 3;           // rows 0..63, chunks 0..3
    const __half* srcA = g_keys_h + (size_t)(grow0 + cr) * H_ + cc * 8;
    const __half* srcB = g_UaT_h  + (size_t)(h0 + cr) * H_ + cc * 8;
    const uint32_t dstA = sb + swb(cr, cc);
    const uint32_t dstB = sb + OFS_B + swb(cr, cc);

    #define ISSUE_STAGE(off) do {                                           \
        cpasync16(dstA + (off),        srcA);                               \
        cpasync16(dstA + (off) + 4096, srcA + 64 * H_);                     \
        cpasync16(dstB + (off),        srcB);                               \
        cpasync16(dstB + (off) + 4096, srcB + 64 * H_);                     \
        srcA += 32; srcB += 32;                                             \
    } while (0)

    // ---- ldmatrix bases (include sb) ----
    const int lrow = lane & 15, lcol = lane >> 4;
    uint32_t aoff[2], boff[2];
    #pragma unroll
    for (int ks = 0; ks < 2; ks++) {
        aoff[ks] = sb + swb(wm * 32 + lrow, ks * 2 + lcol);
        boff[ks] = sb + OFS_B + swb(wn * 64 + lrow, ks * 2 + lcol);
    }

    float acc[2][8][4];
    #pragma unroll
    for (int i = 0; i < 2; i++)
        #pragma unroll
        for (int j = 0; j < 8; j++)
            #pragma unroll
            for (int q = 0; q < 4; q++) acc[i][j][q] = 0.f;

    #define COMPUTE_STAGE(off) do {                                         \
        _Pragma("unroll")                                                   \
        for (int ks = 0; ks < 2; ks++) {                                    \
            uint32_t ah[2][4];                                              \
            ldsm4(ah[0], aoff[ks] + (off));                                 \
            ldsm4(ah[1], aoff[ks] + (off) + 1024);                          \
            _Pragma("unroll")                                               \
            for (int ng = 0; ng < 4; ng++) {                                \
                uint32_t bh[4];                                             \
                ldsm4(bh, boff[ks] + (off) + ng * 1024);                    \
                const int nf = ng * 2;                                      \
                mma_f32(acc[0][nf],     ah[0], bh[0], bh[2]);               \
                mma_f32(acc[0][nf + 1], ah[0], bh[1], bh[3]);               \
                mma_f32(acc[1][nf],     ah[1], bh[0], bh[2]);               \
                mma_f32(acc[1][nf + 1], ah[1], bh[1], bh[3]);               \
            }                                                               \
        }                                                                   \
    } while (0)

    #define ITER_FULL(u) do {                                               \
        CP_WAIT2();                                                         \
        __syncthreads();                                                    \
        ISSUE_STAGE((((u) + 3) & 3) * STAGE);                               \
        CP_COMMIT();                                                        \
        COMPUTE_STAGE((u) * STAGE);                                         \
    } while (0)
    #define ITER_TAIL(u) do {                                               \
        CP_WAIT2();                                                         \
        __syncthreads();                                                    \
        CP_COMMIT();                                                        \
        COMPUTE_STAGE((u) * STAGE);                                         \
    } while (0)

    // prologue: stages 0..2
    ISSUE_STAGE(0 * STAGE); CP_COMMIT();
    ISSUE_STAGE(1 * STAGE); CP_COMMIT();
    ISSUE_STAGE(2 * STAGE); CP_COMMIT();

    // iters 0..27 (7 blocks of 4, constant stage offsets)
    #pragma unroll 1
    for (int ob = 0; ob < 7; ob++) {
        ITER_FULL(0);
        ITER_FULL(1);
        ITER_FULL(2);
        ITER_FULL(3);
    }
    // iter 28 (last refill: stage 31 into buffer 3), then 29..31
    ITER_FULL(0);
    ITER_TAIL(1);
    ITER_TAIL(2);
    ITER_TAIL(3);

    // ---- epilogue: p[row] = sum_h tanh(acc + q[h]) * Va[h] ----
    float pr[2][2] = {{0.f, 0.f}, {0.f, 0.f}};
    #pragma unroll
    for (int ms = 0; ms < 2; ms++) {
        #pragma unroll
        for (int nf = 0; nf < 8; nf++) {
            int col = wn * 64 + nf * 8 + (lane & 3) * 2;
            float q0v = qs[col], q1v = qs[col + 1];
            float v0v = vs[col], v1v = vs[col + 1];
            pr[ms][0] += tanh_fast(acc[ms][nf][0] + q0v) * v0v
                       + tanh_fast(acc[ms][nf][1] + q1v) * v1v;
            pr[ms][1] += tanh_fast(acc[ms][nf][2] + q0v) * v0v
                       + tanh_fast(acc[ms][nf][3] + q1v) * v1v;
        }
    }
    #pragma unroll
    for (int ms = 0; ms < 2; ms++)
        #pragma unroll
        for (int hf = 0; hf < 2; hf++) {
            pr[ms][hf] += __shfl_xor_sync(0xFFFFFFFFu, pr[ms][hf], 1);
            pr[ms][hf] += __shfl_xor_sync(0xFFFFFFFFu, pr[ms][hf], 2);
        }

    __syncthreads();
    float* red = (float*)smem;            // 2 x 128 floats (stages dead)
    if ((lane & 3) == 0) {
        #pragma unroll
        for (int ms = 0; ms < 2; ms++) {
            int row = wm * 32 + ms * 16 + (lane >> 2);
            red[wn * 128 + row]     = pr[ms][0];
            red[wn * 128 + row + 8] = pr[ms][1];
        }
    }
    __syncthreads();
    if (tid < 128)
        g_spart[(size_t)blockIdx.x * MROWS + grow0 + tid] = red[tid] + red[128 + tid];
}

// ============================================================
// K3: softmax over S per batch (8 h-block partials)
// ============================================================
__global__ __launch_bounds__(256) void softmax_kernel(float* __restrict__ weights)
{
    const int b = blockIdx.x;
    const int tid = threadIdx.x;
    const int lane = tid & 31, wid = tid >> 5;
    __shared__ float sred[8];

    float v[8];
    #pragma unroll
    for (int i = 0; i < 8; i++) {
        int s = tid + i * 256;
        float t = 0.f;
        #pragma unroll
        for (int hb = 0; hb < 8; hb++)
            t += g_spart[(size_t)hb * MROWS + (size_t)b * S_ + s];
        v[i] = t;
    }
    float m = v[0];
    #pragma unroll
    for (int i = 1; i < 8; i++) m = fmaxf(m, v[i]);
    #pragma unroll
    for (int off = 16; off > 0; off >>= 1)
        m = fmaxf(m, __shfl_xor_sync(0xFFFFFFFFu, m, off));
    if (lane == 0) sred[wid] = m;
    __syncthreads();
    float mm = sred[0];
    #pragma unroll
    for (int w = 1; w < 8; w++) mm = fmaxf(mm, sred[w]);
    __syncthreads();
    float sum = 0.f;
    #pragma unroll
    for (int i = 0; i < 8; i++) { v[i] = __expf(v[i] - mm); sum += v[i]; }
    #pragma unroll
    for (int off = 16; off > 0; off >>= 1)
        sum += __shfl_xor_sync(0xFFFFFFFFu, sum, off);
    if (lane == 0) sred[wid] = sum;
    __syncthreads();
    float tot = 0.f;
    #pragma unroll
    for (int w = 0; w < 8; w++) tot += sred[w];
    float inv = 1.0f / tot;
    #pragma unroll
    for (int i = 0; i < 8; i++)
        weights[(size_t)b * S_ + tid + i * 256] = v[i] * inv;
}

// ============================================================
// K4: context partials, half2 loads, 16-way S split, atomic accumulate.
// grid (2, B, 16). ctx zeroed by preprocess.
// ============================================================
__global__ __launch_bounds__(256) void context_part_kernel(
    const float* __restrict__ weights, float* __restrict__ ctx)
{
    const int b = blockIdx.y, sc = blockIdx.z;
    const int h2 = blockIdx.x * 256 + threadIdx.x;    // half2 index, 0..511
    __shared__ float sw[128];
    if (threadIdx.x < 128)
        sw[threadIdx.x] = weights[(size_t)b * S_ + sc * 128 + threadIdx.x];
    __syncthreads();

    const __half2* kb = (const __half2*)g_keys_h
                        + ((size_t)b * S_ + (size_t)sc * 128) * (H_ / 2) + h2;
    float ax0 = 0.f, ay0 = 0.f, ax1 = 0.f, ay1 = 0.f;
    #pragma unroll 4
    for (int s = 0; s < 128; s += 2) {
        float2 k0 = __half22float2(kb[(size_t)(s + 0) * (H_ / 2)]);
        float2 k1 = __half22float2(kb[(size_t)(s + 1) * (H_ / 2)]);
        ax0 = fmaf(sw[s + 0], k0.x, ax0);
        ay0 = fmaf(sw[s + 0], k0.y, ay0);
        ax1 = fmaf(sw[s + 1], k1.x, ax1);
        ay1 = fmaf(sw[s + 1], k1.y, ay1);
    }
    float* dst = ctx + (size_t)b * H_ + h2 * 2;
    atomicAdd(dst,     ax0 + ax1);
    atomicAdd(dst + 1, ay0 + ay1);
}

// ============================================================
extern "C" void kernel_launch(void* const* d_in, const int* in_sizes, int n_in,
                              void* d_out, int out_size)
{
    const float* query = (const float*)d_in[0];
    const float* keys  = (const float*)d_in[1];
    const float* Wa_w  = (const float*)d_in[2];
    const float* Wa_b  = (const float*)d_in[3];
    const float* Ua_w  = (const float*)d_in[4];
    const float* Ua_b  = (const float*)d_in[5];
    const float* Va_w  = (const float*)d_in[6];
    // Va_b: constant shift of scores, cancels in softmax.

    float* ctx = (float*)d_out;
    float* wts = (float*)d_out + B_ * H_;

    cudaFuncSetAttribute(score_kernel,
                         cudaFuncAttributeMaxDynamicSharedMemorySize, SMEM_SCORE);

    preprocess_kernel<<<3616, 256>>>(keys, Ua_w, query, Wa_w, ctx);
    score_kernel<<<dim3(8, 512), 256, SMEM_SCORE>>>(Va_w, Wa_b, Ua_b);
    softmax_kernel<<<B_, 256>>>(wts);
    context_part_kernel<<<dim3(2, B_, 16), 256>>>(wts, ctx);
}

// round 17
// speedup vs baseline: 1.0614x; 1.0115x over previous
#include <cuda_runtime.h>
#include <cuda_fp16.h>
#include <math.h>
#include <stdint.h>

#define B_ 32
#define S_ 2048
#define H_ 1024
#define D_ 2048     // H * L
#define MROWS 65536 // B*S

// ---------------- scratch (device globals; no runtime alloc) ----------------
__device__ float g_qpart[8 * B_ * H_];                     // qproj k-split partials
__device__ float g_spart[8 * MROWS];                       // partial scores per 128-h block
__device__ __align__(128) __half g_keys_h[(size_t)MROWS * H_];   // keys fp16 (rn)
__device__ __align__(128) __half g_UaT_h[H_ * H_];         // Ua^T fp16 (rn) [h][d]

// ---------------- PTX helpers (base PTX only) ----------------
__device__ __forceinline__ uint32_t smem_u32(const void* p) {
    uint32_t a;
    asm("{ .reg .u64 t; cvta.to.shared.u64 t, %1; cvt.u32.u64 %0, t; }" : "=r"(a) : "l"(p));
    return a;
}
__device__ __forceinline__ void cpasync16(uint32_t dst, const void* src) {
    asm volatile("cp.async.cg.shared.global [%0], [%1], 16;" :: "r"(dst), "l"(src));
}
#define CP_COMMIT() asm volatile("cp.async.commit_group;" ::: "memory")
#define CP_WAIT2()  asm volatile("cp.async.wait_group 2;" ::: "memory")

__device__ __forceinline__ void ldsm4(uint32_t (&r)[4], uint32_t a) {
    asm volatile("ldmatrix.sync.aligned.m8n8.x4.shared.b16 {%0,%1,%2,%3}, [%4];"
                 : "=r"(r[0]), "=r"(r[1]), "=r"(r[2]), "=r"(r[3]) : "r"(a));
}
__device__ __forceinline__ void mma_f32(float (&d)[4], const uint32_t (&a)[4],
                                        uint32_t b0, uint32_t b1) {
    asm volatile(
        "mma.sync.aligned.m16n8k16.row.col.f32.f16.f16.f32 "
        "{%0,%1,%2,%3}, {%4,%5,%6,%7}, {%8,%9}, {%0,%1,%2,%3};"
        : "+f"(d[0]), "+f"(d[1]), "+f"(d[2]), "+f"(d[3])
        : "r"(a[0]), "r"(a[1]), "r"(a[2]), "r"(a[3]), "r"(b0), "r"(b1));
}

// pair-line swizzle: 64B rows, two rows per 128B line; steps of 16 rows = +1024B,
// 64 rows = +4096B (swizzle bits invariant).
__device__ __forceinline__ uint32_t swb(int r, int c) {
    return (uint32_t)((r >> 1) * 128 + ((((r & 1) << 2) | c) ^ ((r >> 1) & 7)) * 16);
}

__device__ __forceinline__ float tanh_fast(float x) {
    float e = __expf(-2.f * fabsf(x));
    return copysignf(__fdividef(1.f - e, 1.f + e), x);
}

// ============================================================
// P0 (fused preprocess): one launch, blockIdx ranges.
//  [0, 2048):    keys fp32 -> fp16 grid-stride split
//  [2048, 3072): Ua transpose + fp16
//  [3072, 3584): qproj partials (2-batch, 8-way K-split)
//  [3584, 3616): zero ctx (for context atomics)
// ============================================================
__global__ __launch_bounds__(256) void preprocess_kernel(
    const float* __restrict__ keys, const float* __restrict__ Ua,
    const float* __restrict__ query, const float* __restrict__ Wa,
    float* __restrict__ ctx)
{
    __shared__ float tile[32][33];
    const int bid = blockIdx.x;

    if (bid < 2048) {
        // ---- keys split ----
        const size_t stride = (size_t)2048 * 256 * 8;
        size_t base = ((size_t)bid * 256 + threadIdx.x) * 8;
        #pragma unroll 4
        for (int it = 0; it < 16; it++) {
            size_t i = base + (size_t)it * stride;
            float4 v0 = *(const float4*)(keys + i);
            float4 v1 = *(const float4*)(keys + i + 4);
            __half2 h0 = __floats2half2_rn(v0.x, v0.y);
            __half2 h1 = __floats2half2_rn(v0.z, v0.w);
            __half2 h2 = __floats2half2_rn(v1.x, v1.y);
            __half2 h3 = __floats2half2_rn(v1.z, v1.w);
            uint4 o;
            o.x = *(uint32_t*)&h0; o.y = *(uint32_t*)&h1;
            o.z = *(uint32_t*)&h2; o.w = *(uint32_t*)&h3;
            *(uint4*)(g_keys_h + i) = o;
        }
    } else if (bid < 3072) {
        // ---- Ua transpose + fp16 ----
        int id = bid - 2048;
        int tx = threadIdx.x & 31, ty = threadIdx.x >> 5;
        int x0 = (id & 31) * 32, y0 = (id >> 5) * 32;   // x: h, y: d
        #pragma unroll
        for (int j = 0; j < 4; j++)
            tile[ty + j * 8][tx] = Ua[(size_t)(y0 + ty + j * 8) * H_ + x0 + tx];
        __syncthreads();
        #pragma unroll
        for (int j = 0; j < 4; j++) {
            float v = tile[tx][ty + j * 8];
            g_UaT_h[(size_t)(x0 + ty + j * 8) * H_ + y0 + tx] = __float2half_rn(v);
        }
    } else if (bid < 3584) {
        // ---- qproj partials ----
        int id = bid - 3072;                 // 512 blocks: 4 hx * 16 bgrp * 8 kc
        int hx = id & 3;
        int b0 = ((id >> 2) & 15) * 2;
        int kc = id >> 6;
        const int h = hx * 256 + threadIdx.x;
        const float* q0 = query + (size_t)(b0 + 0) * D_ + kc * 256;
        const float* q1 = query + (size_t)(b0 + 1) * D_ + kc * 256;
        const float* w  = Wa + (size_t)kc * 256 * H_ + h;
        float a0 = 0.f, a1 = 0.f;
        #pragma unroll 8
        for (int d = 0; d < 256; d++) {
            float wv = w[(size_t)d * H_];
            a0 = fmaf(q0[d], wv, a0);
            a1 = fmaf(q1[d], wv, a1);
        }
        float* dst = g_qpart + (size_t)kc * (B_ * H_) + (size_t)b0 * H_ + h;
        dst[0]  = a0;
        dst[H_] = a1;
    } else {
        // ---- zero ctx (B_*H_ = 32768 floats; 32 blocks x 256 thr x 4) ----
        int id = bid - 3584;
        int i = (id * 256 + threadIdx.x) * 4;
        *(float4*)(ctx + i) = make_float4(0.f, 0.f, 0.f, 0.f);
    }
}

// ============================================================
// K2: mma.sync score kernel v13 — r14 config + double-buffered B frags.
// 256 threads, CTA 128(s) x 128(h), 8 warps (4m x 2n), warp 32x64.
// BK=32, 4-stage cp.async (wait_group 2), 2 CTAs/SM, unrolled.
// grid (8 hblk, 512 sblk), h fastest for L2 reuse of A.
// ============================================================
#define STAGE  16384          // A 8K | B 8K
#define OFS_B  8192
#define NSTG   4
#define SMEM_SCORE (NSTG * STAGE + 1024)

__global__ __launch_bounds__(256, 2) void score_kernel(
    const float* __restrict__ Va,
    const float* __restrict__ Wab, const float* __restrict__ Uab)
{
    extern __shared__ char smem[];
    const uint32_t sb = smem_u32(smem);
    const int tid  = threadIdx.x;
    const int wid  = tid >> 5, lane = tid & 31;
    const int wm   = wid & 3,  wn   = wid >> 2;      // 4m x 2n warp grid

    const int h0    = blockIdx.x * 128;
    const int grow0 = blockIdx.y * 128;
    const int b     = grow0 >> 11;

    float* qs = (float*)(smem + NSTG * STAGE);
    float* vs = qs + 128;
    if (tid < 128) {
        int h = h0 + tid;
        float s = Wab[h] + Uab[h];
        #pragma unroll
        for (int c = 0; c < 8; c++)
            s += g_qpart[(size_t)c * (B_ * H_) + (size_t)b * H_ + h];
        qs[tid] = s;
        vs[tid] = Va[h];
    }

    // ---- cp.async setup (bases include sb; stage offsets are immediates) ----
    const int cr = tid >> 2, cc = tid & 3;           // rows 0..63, chunks 0..3
    const __half* srcA = g_keys_h + (size_t)(grow0 + cr) * H_ + cc * 8;
    const __half* srcB = g_UaT_h  + (size_t)(h0 + cr) * H_ + cc * 8;
    const uint32_t dstA = sb + swb(cr, cc);
    const uint32_t dstB = sb + OFS_B + swb(cr, cc);

    #define ISSUE_STAGE(off) do {                                           \
        cpasync16(dstA + (off),        srcA);                               \
        cpasync16(dstA + (off) + 4096, srcA + 64 * H_);                     \
        cpasync16(dstB + (off),        srcB);                               \
        cpasync16(dstB + (off) + 4096, srcB + 64 * H_);                     \
        srcA += 32; srcB += 32;                                             \
    } while (0)

    // ---- ldmatrix bases (include sb) ----
    const int lrow = lane & 15, lcol = lane >> 4;
    uint32_t aoff[2], boff[2];
    #pragma unroll
    for (int ks = 0; ks < 2; ks++) {
        aoff[ks] = sb + swb(wm * 32 + lrow, ks * 2 + lcol);
        boff[ks] = sb + OFS_B + swb(wn * 64 + lrow, ks * 2 + lcol);
    }

    float acc[2][8][4];
    #pragma unroll
    for (int i = 0; i < 2; i++)
        #pragma unroll
        for (int j = 0; j < 8; j++)
            #pragma unroll
            for (int q = 0; q < 4; q++) acc[i][j][q] = 0.f;

    // B fragments double-buffered: ldsm for group ng+1 issues before the
    // MMAs consuming group ng, hiding ldsm latency behind MMA issue.
    #define COMPUTE_STAGE(off) do {                                         \
        _Pragma("unroll")                                                   \
        for (int ks = 0; ks < 2; ks++) {                                    \
            uint32_t ah[2][4];                                              \
            ldsm4(ah[0], aoff[ks] + (off));                                 \
            ldsm4(ah[1], aoff[ks] + (off) + 1024);                          \
            uint32_t bhb[2][4];                                             \
            ldsm4(bhb[0], boff[ks] + (off));                                \
            _Pragma("unroll")                                               \
            for (int ng = 0; ng < 4; ng++) {                                \
                const int cur = ng & 1;                                     \
                if (ng < 3)                                                 \
                    ldsm4(bhb[cur ^ 1], boff[ks] + (off) + (ng + 1) * 1024);\
                const int nf = ng * 2;                                      \
                mma_f32(acc[0][nf],     ah[0], bhb[cur][0], bhb[cur][2]);   \
                mma_f32(acc[0][nf + 1], ah[0], bhb[cur][1], bhb[cur][3]);   \
                mma_f32(acc[1][nf],     ah[1], bhb[cur][0], bhb[cur][2]);   \
                mma_f32(acc[1][nf + 1], ah[1], bhb[cur][1], bhb[cur][3]);   \
            }                                                               \
        }                                                                   \
    } while (0)

    #define ITER_FULL(u) do {                                               \
        CP_WAIT2();                                                         \
        __syncthreads();                                                    \
        ISSUE_STAGE((((u) + 3) & 3) * STAGE);                               \
        CP_COMMIT();                                                        \
        COMPUTE_STAGE((u) * STAGE);                                         \
    } while (0)
    #define ITER_TAIL(u) do {                                               \
        CP_WAIT2();                                                         \
        __syncthreads();                                                    \
        CP_COMMIT();                                                        \
        COMPUTE_STAGE((u) * STAGE);                                         \
    } while (0)

    // prologue: stages 0..2
    ISSUE_STAGE(0 * STAGE); CP_COMMIT();
    ISSUE_STAGE(1 * STAGE); CP_COMMIT();
    ISSUE_STAGE(2 * STAGE); CP_COMMIT();

    // iters 0..27 (7 blocks of 4, constant stage offsets)
    #pragma unroll 1
    for (int ob = 0; ob < 7; ob++) {
        ITER_FULL(0);
        ITER_FULL(1);
        ITER_FULL(2);
        ITER_FULL(3);
    }
    // iter 28 (last refill: stage 31 into buffer 3), then 29..31
    ITER_FULL(0);
    ITER_TAIL(1);
    ITER_TAIL(2);
    ITER_TAIL(3);

    // ---- epilogue: p[row] = sum_h tanh(acc + q[h]) * Va[h] ----
    float pr[2][2] = {{0.f, 0.f}, {0.f, 0.f}};
    #pragma unroll
    for (int ms = 0; ms < 2; ms++) {
        #pragma unroll
        for (int nf = 0; nf < 8; nf++) {
            int col = wn * 64 + nf * 8 + (lane & 3) * 2;
            float q0v = qs[col], q1v = qs[col + 1];
            float v0v = vs[col], v1v = vs[col + 1];
            pr[ms][0] += tanh_fast(acc[ms][nf][0] + q0v) * v0v
                       + tanh_fast(acc[ms][nf][1] + q1v) * v1v;
            pr[ms][1] += tanh_fast(acc[ms][nf][2] + q0v) * v0v
                       + tanh_fast(acc[ms][nf][3] + q1v) * v1v;
        }
    }
    #pragma unroll
    for (int ms = 0; ms < 2; ms++)
        #pragma unroll
        for (int hf = 0; hf < 2; hf++) {
            pr[ms][hf] += __shfl_xor_sync(0xFFFFFFFFu, pr[ms][hf], 1);
            pr[ms][hf] += __shfl_xor_sync(0xFFFFFFFFu, pr[ms][hf], 2);
        }

    __syncthreads();
    float* red = (float*)smem;            // 2 x 128 floats (stages dead)
    if ((lane & 3) == 0) {
        #pragma unroll
        for (int ms = 0; ms < 2; ms++) {
            int row = wm * 32 + ms * 16 + (lane >> 2);
            red[wn * 128 + row]     = pr[ms][0];
            red[wn * 128 + row + 8] = pr[ms][1];
        }
    }
    __syncthreads();
    if (tid < 128)
        g_spart[(size_t)blockIdx.x * MROWS + grow0 + tid] = red[tid] + red[128 + tid];
}

// ============================================================
// K3: softmax over S per batch (8 h-block partials)
// ============================================================
__global__ __launch_bounds__(256) void softmax_kernel(float* __restrict__ weights)
{
    const int b = blockIdx.x;
    const int tid = threadIdx.x;
    const int lane = tid & 31, wid = tid >> 5;
    __shared__ float sred[8];

    float v[8];
    #pragma unroll
    for (int i = 0; i < 8; i++) {
        int s = tid + i * 256;
        float t = 0.f;
        #pragma unroll
        for (int hb = 0; hb < 8; hb++)
            t += g_spart[(size_t)hb * MROWS + (size_t)b * S_ + s];
        v[i] = t;
    }
    float m = v[0];
    #pragma unroll
    for (int i = 1; i < 8; i++) m = fmaxf(m, v[i]);
    #pragma unroll
    for (int off = 16; off > 0; off >>= 1)
        m = fmaxf(m, __shfl_xor_sync(0xFFFFFFFFu, m, off));
    if (lane == 0) sred[wid] = m;
    __syncthreads();
    float mm = sred[0];
    #pragma unroll
    for (int w = 1; w < 8; w++) mm = fmaxf(mm, sred[w]);
    __syncthreads();
    float sum = 0.f;
    #pragma unroll
    for (int i = 0; i < 8; i++) { v[i] = __expf(v[i] - mm); sum += v[i]; }
    #pragma unroll
    for (int off = 16; off > 0; off >>= 1)
        sum += __shfl_xor_sync(0xFFFFFFFFu, sum, off);
    if (lane == 0) sred[wid] = sum;
    __syncthreads();
    float tot = 0.f;
    #pragma unroll
    for (int w = 0; w < 8; w++) tot += sred[w];
    float inv = 1.0f / tot;
    #pragma unroll
    for (int i = 0; i < 8; i++)
        weights[(size_t)b * S_ + tid + i * 256] = v[i] * inv;
}

// ============================================================
// K4: context partials, half2 loads, 16-way S split, atomic accumulate.
// grid (2, B, 16). ctx zeroed by preprocess.
// ============================================================
__global__ __launch_bounds__(256) void context_part_kernel(
    const float* __restrict__ weights, float* __restrict__ ctx)
{
    const int b = blockIdx.y, sc = blockIdx.z;
    const int h2 = blockIdx.x * 256 + threadIdx.x;    // half2 index, 0..511
    __shared__ float sw[128];
    if (threadIdx.x < 128)
        sw[threadIdx.x] = weights[(size_t)b * S_ + sc * 128 + threadIdx.x];
    __syncthreads();

    const __half2* kb = (const __half2*)g_keys_h
                        + ((size_t)b * S_ + (size_t)sc * 128) * (H_ / 2) + h2;
    float ax0 = 0.f, ay0 = 0.f, ax1 = 0.f, ay1 = 0.f;
    #pragma unroll 4
    for (int s = 0; s < 128; s += 2) {
        float2 k0 = __half22float2(kb[(size_t)(s + 0) * (H_ / 2)]);
        float2 k1 = __half22float2(kb[(size_t)(s + 1) * (H_ / 2)]);
        ax0 = fmaf(sw[s + 0], k0.x, ax0);
        ay0 = fmaf(sw[s + 0], k0.y, ay0);
        ax1 = fmaf(sw[s + 1], k1.x, ax1);
        ay1 = fmaf(sw[s + 1], k1.y, ay1);
    }
    float* dst = ctx + (size_t)b * H_ + h2 * 2;
    atomicAdd(dst,     ax0 + ax1);
    atomicAdd(dst + 1, ay0 + ay1);
}

// ============================================================
extern "C" void kernel_launch(void* const* d_in, const int* in_sizes, int n_in,
                              void* d_out, int out_size)
{
    const float* query = (const float*)d_in[0];
    const float* keys  = (const float*)d_in[1];
    const float* Wa_w  = (const float*)d_in[2];
    const float* Wa_b  = (const float*)d_in[3];
    const float* Ua_w  = (const float*)d_in[4];
    const float* Ua_b  = (const float*)d_in[5];
    const float* Va_w  = (const float*)d_in[6];
    // Va_b: constant shift of scores, cancels in softmax.

    float* ctx = (float*)d_out;
    float* wts = (float*)d_out + B_ * H_;

    cudaFuncSetAttribute(score_kernel,
                         cudaFuncAttributeMaxDynamicSharedMemorySize, SMEM_SCORE);

    preprocess_kernel<<<3616, 256>>>(keys, Ua_w, query, Wa_w, ctx);
    score_kernel<<<dim3(8, 512), 256, SMEM_SCORE>>>(Va_w, Wa_b, Ua_b);
    softmax_kernel<<<B_, 256>>>(wts);
    context_part_kernel<<<dim3(2, B_, 16), 256>>>(wts, ctx);
}